// round 1
// baseline (speedup 1.0000x reference)
#include <cuda_runtime.h>
#include <cstdint>
#include <math.h>

#define B_ 32
#define C_ 64
#define M_ 9216
#define CHUNK 256
#define NCH 36           // 9216 / 256
#define TM 64            // m-tile staged in smem
#define SMSTRIDE 66      // [m][c] layout pad (keeps float2 loads 8B aligned, breaks bank patterns)

typedef unsigned long long ull;

// Scratch (no allocations allowed -> __device__ globals)
__device__ __align__(16) float g_gram_part[NCH * B_ * C_ * C_];  // 18.9 MB
__device__ __align__(16) float g_sum_part[NCH * B_ * C_];
__device__ float g_gate[B_ * C_];

__device__ __forceinline__ ull dup2(float v) {
    ull r; asm("mov.b64 %0, {%1, %1};" : "=l"(r) : "f"(v)); return r;
}
__device__ __forceinline__ ull pack2(float x, float y) {
    ull r; asm("mov.b64 %0, {%1, %2};" : "=l"(r) : "f"(x), "f"(y)); return r;
}
__device__ __forceinline__ void ffma2(ull& d, ull a, ull b) {
    asm("fma.rn.f32x2 %0, %1, %2, %0;" : "+l"(d) : "l"(a), "l"(b));
}

// ---------------------------------------------------------------------------
// Kernel 1: per-(batch, m-chunk) partial Gram G = sum_m x x^T and channel sums.
// 64 threads, each owns an 8x8 tile of the 64x64 output; f32x2 packed FMAs.
// ---------------------------------------------------------------------------
__global__ void __launch_bounds__(64) gram_kernel(const float* __restrict__ x) {
    __shared__ __align__(16) float sm[TM * SMSTRIDE];
    const int bi  = blockIdx.y;
    const int ch  = blockIdx.x;
    const int tid = threadIdx.x;
    const int ti = tid >> 3, tj = tid & 7;
    const int rbase = ti * 8, cbase = tj * 8;
    const int m_lane = tid & 15, c_grp = tid >> 4;

    ull acc[8][4];
#pragma unroll
    for (int r = 0; r < 8; r++)
#pragma unroll
        for (int q = 0; q < 4; q++) acc[r][q] = 0ull;
    float csum = 0.f;

    const float* xb = x + ((size_t)bi * C_) * M_ + ch * CHUNK;

    for (int t = 0; t < CHUNK / TM; t++) {
        __syncthreads();
        // Stage 64(m) x 64(c) tile transposed into sm[m][c] (coalesced gmem reads)
#pragma unroll
        for (int ci = 0; ci < 16; ci++) {
            int c = ci * 4 + c_grp;
            float4 v = *reinterpret_cast<const float4*>(xb + (size_t)c * M_ + t * TM + 4 * m_lane);
            int ml = 4 * m_lane;
            sm[(ml + 0) * SMSTRIDE + c] = v.x;
            sm[(ml + 1) * SMSTRIDE + c] = v.y;
            sm[(ml + 2) * SMSTRIDE + c] = v.z;
            sm[(ml + 3) * SMSTRIDE + c] = v.w;
        }
        __syncthreads();
#pragma unroll 4
        for (int m = 0; m < TM; m++) {
            const float* row = sm + m * SMSTRIDE;
            ull bb0 = *reinterpret_cast<const ull*>(row + cbase);
            ull bb1 = *reinterpret_cast<const ull*>(row + cbase + 2);
            ull bb2 = *reinterpret_cast<const ull*>(row + cbase + 4);
            ull bb3 = *reinterpret_cast<const ull*>(row + cbase + 6);
#pragma unroll
            for (int r = 0; r < 8; r++) {
                ull a2 = dup2(row[rbase + r]);
                ffma2(acc[r][0], a2, bb0);
                ffma2(acc[r][1], a2, bb1);
                ffma2(acc[r][2], a2, bb2);
                ffma2(acc[r][3], a2, bb3);
            }
        }
        // channel partial sums: thread tid owns channel tid (conflict-free column reads)
#pragma unroll 8
        for (int m = 0; m < TM; m++) csum += sm[m * SMSTRIDE + tid];
    }

    float* gp = g_gram_part + ((size_t)(ch * B_ + bi) << 12);
#pragma unroll
    for (int r = 0; r < 8; r++) {
        ull* dst = reinterpret_cast<ull*>(gp + (rbase + r) * 64 + cbase);
        dst[0] = acc[r][0]; dst[1] = acc[r][1]; dst[2] = acc[r][2]; dst[3] = acc[r][3];
    }
    g_sum_part[(ch * B_ + bi) * C_ + tid] = csum;
}

// ---------------------------------------------------------------------------
// 64x64 matmul helper: C = fA(A) @ fB(B), f(X) = 0.5*(3I - X) when flag set.
// 256 threads, 4x4 tile per thread, stride-64 smem, f32x2 FMAs.
// ---------------------------------------------------------------------------
template <bool FA, bool FB>
__device__ __forceinline__ void mm64(ull acc[4][2], const float* __restrict__ A,
                                     const float* __restrict__ Bm, int r0, int c0) {
#pragma unroll
    for (int q = 0; q < 4; q++) { acc[q][0] = 0ull; acc[q][1] = 0ull; }
#pragma unroll 4
    for (int k = 0; k < 64; k++) {
        float a[4];
#pragma unroll
        for (int r = 0; r < 4; r++) {
            float v = A[(r0 + r) * 64 + k];
            if (FA) v = ((r0 + r == k) ? 1.5f : 0.0f) - 0.5f * v;
            a[r] = v;
        }
        ull bb[2];
        if (FB) {
#pragma unroll
            for (int q = 0; q < 2; q++) {
                float2 bv = *reinterpret_cast<const float2*>(Bm + k * 64 + c0 + 2 * q);
                bv.x = ((k == c0 + 2 * q)     ? 1.5f : 0.0f) - 0.5f * bv.x;
                bv.y = ((k == c0 + 2 * q + 1) ? 1.5f : 0.0f) - 0.5f * bv.y;
                bb[q] = pack2(bv.x, bv.y);
            }
        } else {
            bb[0] = *reinterpret_cast<const ull*>(Bm + k * 64 + c0);
            bb[1] = *reinterpret_cast<const ull*>(Bm + k * 64 + c0 + 2);
        }
#pragma unroll
        for (int r = 0; r < 4; r++) {
            ull a2 = dup2(a[r]);
            ffma2(acc[r][0], a2, bb[0]);
            ffma2(acc[r][1], a2, bb[1]);
        }
    }
}

__device__ __forceinline__ void mm_store(const ull acc[4][2], float* __restrict__ Cm,
                                         int r0, int c0) {
#pragma unroll
    for (int r = 0; r < 4; r++) {
        ull* dst = reinterpret_cast<ull*>(Cm + (r0 + r) * 64 + c0);
        dst[0] = acc[r][0]; dst[1] = acc[r][1];
    }
}

// ---------------------------------------------------------------------------
// Kernel 2: per-batch -> reduce partials, center -> cov, Newton-Schulz sqrt,
// column-mean, bottleneck MLP, sigmoid gate.
// ---------------------------------------------------------------------------
__global__ void __launch_bounds__(256) ns_kernel(const float* __restrict__ gw1,
                                                 const float* __restrict__ gb1,
                                                 const float* __restrict__ gw2,
                                                 const float* __restrict__ gb2) {
    __shared__ __align__(16) float s0[4096];
    __shared__ __align__(16) float s1[4096];
    __shared__ __align__(16) float s2[4096];
    const int bi  = blockIdx.x;
    const int tid = threadIdx.x;
    const int ti = tid >> 4, tj = tid & 15;
    const int r0 = 4 * ti, c0 = 4 * tj;

    // 1) reduce partial grams -> raw G in s0
    {
        const float4* gp = reinterpret_cast<const float4*>(g_gram_part) + bi * 1024;
#pragma unroll
        for (int it = 0; it < 4; it++) {
            int e = it * 256 + tid;  // float4 index
            float4 a4 = make_float4(0.f, 0.f, 0.f, 0.f);
#pragma unroll 6
            for (int c = 0; c < NCH; c++) {
                float4 v = gp[(size_t)c * (B_ * 1024) + e];
                a4.x += v.x; a4.y += v.y; a4.z += v.z; a4.w += v.w;
            }
            reinterpret_cast<float4*>(s0)[e] = a4;
        }
    }
    // 2) channel means into s2[0..63]
    if (tid < 64) {
        float s = 0.f;
        for (int c = 0; c < NCH; c++) s += g_sum_part[(c * B_ + bi) * C_ + tid];
        s2[tid] = s * (1.0f / M_);
    }
    __syncthreads();
    // 3) cov = G/M - mu mu^T (in place in s0)
    {
        const float invM = 1.0f / M_;
        for (int e = tid; e < 4096; e += 256) {
            int r = e >> 6, c = e & 63;
            s0[e] = s0[e] * invM - s2[r] * s2[c];
        }
    }
    __syncthreads();
    // 4) normA = trace(cov)
    if (tid < 32) {
        float t = s0[tid * 65] + s0[(tid + 32) * 65];
#pragma unroll
        for (int o = 16; o > 0; o >>= 1) t += __shfl_xor_sync(0xffffffffu, t, o);
        if (tid == 0) s2[64] = t;
    }
    __syncthreads();
    const float normA = s2[64];
    const float rnorm = 1.0f / normA;
    // 5) A = cov*rnorm (s0);  Z = 0.5*(3I - A) (s1)
    for (int e = tid; e < 4096; e += 256) {
        int r = e >> 6, c = e & 63;
        float a = s0[e] * rnorm;
        s0[e] = a;
        s1[e] = ((r == c) ? 1.5f : 0.0f) - 0.5f * a;
    }
    __syncthreads();
    // 6) Y = A @ Z -> s2  (normA already consumed into registers)
    {
        ull acc[4][2];
        mm64<false, false>(acc, s0, s1, r0, c0);
        mm_store(acc, s2, r0, c0);
    }
    __syncthreads();
    float* Y = s2; float* Z = s1; float* T = s0;
    // 7) three NS iterations
    for (int it = 0; it < 3; it++) {
        ull accT[4][2];
        mm64<true, false>(accT, Z, Y, r0, c0);   // T = 0.5(3I - Z) @ Y
        mm_store(accT, T, r0, c0);               // T(s0) not read by this matmul
        __syncthreads();
        ull accY[4][2], accZ[4][2];
        mm64<false, false>(accY, Y, T, r0, c0);  // newY = Y @ T
        mm64<false, false>(accZ, T, Z, r0, c0);  // newZ = T @ Z
        __syncthreads();                         // everyone done reading Y,Z
        mm_store(accY, Y, r0, c0);
        mm_store(accZ, Z, r0, c0);
        __syncthreads();
    }
    // 8) W = Z @ Y -> T(s0)
    {
        ull acc[4][2];
        mm64<false, false>(acc, Z, Y, r0, c0);
        mm_store(acc, T, r0, c0);
    }
    __syncthreads();
    // 9) F = Y @ 0.5(3I - W) -> s1 (Z dead)
    {
        ull acc[4][2];
        mm64<false, true>(acc, Y, T, r0, c0);
        mm_store(acc, s1, r0, c0);
    }
    __syncthreads();
    // 10) s_j = sqrt(normA)/64 * sum_i F[i][j]  -> s0[0..63]
    const float scale_s = sqrtf(normA) * (1.0f / 64.0f);
    if (tid < 64) {
        float s = 0.f;
#pragma unroll 8
        for (int i = 0; i < 64; i++) s += s1[i * 64 + tid];
        s0[tid] = s * scale_s;
    }
    __syncthreads();
    // 11) h = relu(s @ w1^T + b1)
    if (tid < 8) {
        float h = gb1[tid];
        const float* wr = gw1 + tid * 64;
        for (int j = 0; j < 64; j++) h += s0[j] * wr[j];
        s0[64 + tid] = fmaxf(h, 0.f);
    }
    __syncthreads();
    // 12) gate = sigmoid(h @ w2^T + b2)
    if (tid < 64) {
        float g = gb2[tid];
        const float* wr = gw2 + tid * 8;
#pragma unroll
        for (int r = 0; r < 8; r++) g += s0[64 + r] * wr[r];
        g_gate[bi * C_ + tid] = 1.0f / (1.0f + expf(-g));
    }
}

// ---------------------------------------------------------------------------
// Kernel 3: out = x * gate[b][c]  (pure HBM streaming, float4)
// ---------------------------------------------------------------------------
__global__ void __launch_bounds__(256) scale_kernel(const float* __restrict__ x,
                                                    float* __restrict__ out) {
    const int total4 = B_ * C_ * (M_ / 4);  // 4,718,592
    int i = blockIdx.x * blockDim.x + threadIdx.x;
    if (i >= total4) return;
    int bc = i / (M_ / 4);
    float g = __ldg(&g_gate[bc]);
    float4 v = reinterpret_cast<const float4*>(x)[i];
    v.x *= g; v.y *= g; v.z *= g; v.w *= g;
    reinterpret_cast<float4*>(out)[i] = v;
}

extern "C" void kernel_launch(void* const* d_in, const int* in_sizes, int n_in,
                              void* d_out, int out_size) {
    const float* x  = (const float*)d_in[0];
    const float* w1 = (const float*)d_in[1];
    const float* b1 = (const float*)d_in[2];
    const float* w2 = (const float*)d_in[3];
    const float* b2 = (const float*)d_in[4];
    float* out = (float*)d_out;

    dim3 g1(NCH, B_);
    gram_kernel<<<g1, 64>>>(x);
    ns_kernel<<<B_, 256>>>(w1, b1, w2, b2);
    const int total4 = B_ * C_ * (M_ / 4);
    scale_kernel<<<(total4 + 255) / 256, 256>>>(x, out);
}

// round 3
// speedup vs baseline: 1.3912x; 1.3912x over previous
#include <cuda_runtime.h>
#include <cstdint>
#include <math.h>

#define B_ 32
#define C_ 64
#define M_ 9216
#define KSPLIT 9
#define KPC (M_ / KSPLIT)      // 1024 k per CTA
#define KCH 32                 // k-chunk width (floats)
#define NCHK (KPC / KCH)       // 32 chunks
#define SMS 36                 // smem row stride (floats), pad 4

typedef unsigned long long ull;

// Scratch (no allocs allowed)
__device__ __align__(16) float g_gram_part[KSPLIT * B_ * C_ * C_];
__device__ __align__(16) float g_sum_part[KSPLIT * B_ * C_];
__device__ float g_gate[B_ * C_];

__device__ __forceinline__ uint32_t cvt_tf32(float v) {
    uint32_t r; asm("cvt.rna.tf32.f32 %0, %1;" : "=r"(r) : "f"(v)); return r;
}
__device__ __forceinline__ void mma_tf32(float (&d)[4], const uint32_t a[4], const uint32_t b[2]) {
    asm volatile(
        "mma.sync.aligned.m16n8k8.row.col.f32.tf32.tf32.f32 "
        "{%0,%1,%2,%3}, {%4,%5,%6,%7}, {%8,%9}, {%0,%1,%2,%3};"
        : "+f"(d[0]), "+f"(d[1]), "+f"(d[2]), "+f"(d[3])
        : "r"(a[0]), "r"(a[1]), "r"(a[2]), "r"(a[3]), "r"(b[0]), "r"(b[1]));
}

// ---------------------------------------------------------------------------
// Kernel 1: tensor-core Gram via warp mma (tf32 split precision).
// CTA = (ks, batch): streams 64ch x 1024k. Output quadrants P = h h^T (warps
// 0-3) and Q = h l^T (warps 4-7); partial G = P + Q + Q^T.
// ---------------------------------------------------------------------------
__global__ void __launch_bounds__(256, 2) gram_tc(const float* __restrict__ x) {
    __shared__ __align__(16) float s_hi[2][64 * SMS];
    __shared__ __align__(16) float s_lo[2][64 * SMS];

    const int ks = blockIdx.x, bi = blockIdx.y;
    const int tid = threadIdx.x;
    const int w = tid >> 5, l = tid & 31;
    const int lq = l >> 2, lr = l & 3;
    const int qd = w >> 2, wq = w & 3;
    const int rbase = (wq >> 1) << 5, cbase = (wq & 1) << 5;

    const int lrow = tid >> 3;       // 0..31
    const int lj = tid & 7;          // float4 index within 32-float chunk

    const float* xb = x + ((size_t)bi * C_) * M_ + (size_t)ks * KPC + 4 * lj;
    const float* p0 = xb + (size_t)lrow * M_;
    const float* p1 = xb + (size_t)(lrow + 32) * M_;

    float acc[2][4][4];
#pragma unroll
    for (int mg = 0; mg < 2; mg++)
#pragma unroll
        for (int j = 0; j < 4; j++)
#pragma unroll
            for (int e = 0; e < 4; e++) acc[mg][j][e] = 0.f;
    float csum0 = 0.f, csum1 = 0.f;

    // ---- stage helper (convert + STS + csum) done inline ----
    float4 cur0 = *reinterpret_cast<const float4*>(p0);
    float4 cur1 = *reinterpret_cast<const float4*>(p1);

    // prologue: stage chunk 0 into buffer 0
    {
        float4 v = cur0;
        csum0 += v.x + v.y + v.z + v.w;
        uint4 h, lo;
        h.x = cvt_tf32(v.x); lo.x = cvt_tf32(v.x - __uint_as_float(h.x));
        h.y = cvt_tf32(v.y); lo.y = cvt_tf32(v.y - __uint_as_float(h.y));
        h.z = cvt_tf32(v.z); lo.z = cvt_tf32(v.z - __uint_as_float(h.z));
        h.w = cvt_tf32(v.w); lo.w = cvt_tf32(v.w - __uint_as_float(h.w));
        *reinterpret_cast<uint4*>(&s_hi[0][lrow * SMS + 4 * lj]) = h;
        *reinterpret_cast<uint4*>(&s_lo[0][lrow * SMS + 4 * lj]) = lo;
        v = cur1;
        csum1 += v.x + v.y + v.z + v.w;
        h.x = cvt_tf32(v.x); lo.x = cvt_tf32(v.x - __uint_as_float(h.x));
        h.y = cvt_tf32(v.y); lo.y = cvt_tf32(v.y - __uint_as_float(h.y));
        h.z = cvt_tf32(v.z); lo.z = cvt_tf32(v.z - __uint_as_float(h.z));
        h.w = cvt_tf32(v.w); lo.w = cvt_tf32(v.w - __uint_as_float(h.w));
        *reinterpret_cast<uint4*>(&s_hi[0][(lrow + 32) * SMS + 4 * lj]) = h;
        *reinterpret_cast<uint4*>(&s_lo[0][(lrow + 32) * SMS + 4 * lj]) = lo;
    }
    __syncthreads();

    for (int c = 0; c < NCHK; c++) {
        const int buf = c & 1;
        float4 nxt0, nxt1;
        if (c + 1 < NCHK) {
            nxt0 = *reinterpret_cast<const float4*>(p0 + (size_t)(c + 1) * KCH);
            nxt1 = *reinterpret_cast<const float4*>(p1 + (size_t)(c + 1) * KCH);
        }

        // mma over current buffer
        const uint32_t* UH = reinterpret_cast<const uint32_t*>(s_hi[buf]);
        const uint32_t* UB = qd ? reinterpret_cast<const uint32_t*>(s_lo[buf]) : UH;
#pragma unroll
        for (int k8 = 0; k8 < 4; k8++) {
            const int k0 = 8 * k8;
            uint32_t a[2][4];
#pragma unroll
            for (int mg = 0; mg < 2; mg++) {
                int r = rbase + 16 * mg + lq;
                a[mg][0] = UH[r * SMS + k0 + lr];
                a[mg][1] = UH[(r + 8) * SMS + k0 + lr];
                a[mg][2] = UH[r * SMS + k0 + 4 + lr];
                a[mg][3] = UH[(r + 8) * SMS + k0 + 4 + lr];
            }
            uint32_t b[4][2];
#pragma unroll
            for (int j = 0; j < 4; j++) {
                int cn = cbase + 8 * j + lq;
                b[j][0] = UB[cn * SMS + k0 + lr];
                b[j][1] = UB[cn * SMS + k0 + 4 + lr];
            }
#pragma unroll
            for (int mg = 0; mg < 2; mg++)
#pragma unroll
                for (int j = 0; j < 4; j++) mma_tf32(acc[mg][j], a[mg], b[j]);
        }

        // stage next chunk into the other buffer
        if (c + 1 < NCHK) {
            const int nb = buf ^ 1;
            float4 v = nxt0;
            csum0 += v.x + v.y + v.z + v.w;
            uint4 h, lo;
            h.x = cvt_tf32(v.x); lo.x = cvt_tf32(v.x - __uint_as_float(h.x));
            h.y = cvt_tf32(v.y); lo.y = cvt_tf32(v.y - __uint_as_float(h.y));
            h.z = cvt_tf32(v.z); lo.z = cvt_tf32(v.z - __uint_as_float(h.z));
            h.w = cvt_tf32(v.w); lo.w = cvt_tf32(v.w - __uint_as_float(h.w));
            *reinterpret_cast<uint4*>(&s_hi[nb][lrow * SMS + 4 * lj]) = h;
            *reinterpret_cast<uint4*>(&s_lo[nb][lrow * SMS + 4 * lj]) = lo;
            v = nxt1;
            csum1 += v.x + v.y + v.z + v.w;
            h.x = cvt_tf32(v.x); lo.x = cvt_tf32(v.x - __uint_as_float(h.x));
            h.y = cvt_tf32(v.y); lo.y = cvt_tf32(v.y - __uint_as_float(h.y));
            h.z = cvt_tf32(v.z); lo.z = cvt_tf32(v.z - __uint_as_float(h.z));
            h.w = cvt_tf32(v.w); lo.w = cvt_tf32(v.w - __uint_as_float(h.w));
            *reinterpret_cast<uint4*>(&s_hi[nb][(lrow + 32) * SMS + 4 * lj]) = h;
            *reinterpret_cast<uint4*>(&s_lo[nb][(lrow + 32) * SMS + 4 * lj]) = lo;
        }
        __syncthreads();
    }

    // ---- epilogue: stage P, Q into smem (stride 65), combine, write partial
    float* P = s_hi[0];   // needs 64*65 = 4160 floats; buffer has 4608
    float* Q = s_lo[0];
    {
        float* Out = qd ? Q : P;
#pragma unroll
        for (int mg = 0; mg < 2; mg++) {
            int r = rbase + 16 * mg + lq;
#pragma unroll
            for (int j = 0; j < 4; j++) {
                int cc = cbase + 8 * j + 2 * lr;
                Out[r * 65 + cc]       = acc[mg][j][0];
                Out[r * 65 + cc + 1]   = acc[mg][j][1];
                Out[(r + 8) * 65 + cc]     = acc[mg][j][2];
                Out[(r + 8) * 65 + cc + 1] = acc[mg][j][3];
            }
        }
    }
    // channel sums: reduce within groups of 8 lanes (same row)
    {
        unsigned full = 0xffffffffu;
#pragma unroll
        for (int o = 4; o > 0; o >>= 1) {
            csum0 += __shfl_xor_sync(full, csum0, o);
            csum1 += __shfl_xor_sync(full, csum1, o);
        }
        if (lj == 0) {
            float* sp = g_sum_part + ((size_t)ks * B_ + bi) * C_;
            sp[lrow] = csum0;
            sp[lrow + 32] = csum1;
        }
    }
    __syncthreads();
    float* gp = g_gram_part + (((size_t)ks * B_ + bi) << 12);
    for (int e = tid; e < 4096; e += 256) {
        int r = e >> 6, cc = e & 63;
        gp[e] = P[r * 65 + cc] + Q[r * 65 + cc] + Q[cc * 65 + r];
    }
}

// ---------------------------------------------------------------------------
// f32x2 helpers for the NS kernel
// ---------------------------------------------------------------------------
__device__ __forceinline__ ull dup2(float v) {
    ull r; asm("mov.b64 %0, {%1, %1};" : "=l"(r) : "f"(v)); return r;
}
__device__ __forceinline__ ull pack2(float x, float y) {
    ull r; asm("mov.b64 %0, {%1, %2};" : "=l"(r) : "f"(x), "f"(y)); return r;
}
__device__ __forceinline__ void ffma2(ull& d, ull a, ull b) {
    asm("fma.rn.f32x2 %0, %1, %2, %0;" : "+l"(d) : "l"(a), "l"(b));
}

template <bool FA, bool FB>
__device__ __forceinline__ void mm64(ull acc[4][2], const float* __restrict__ A,
                                     const float* __restrict__ Bm, int r0, int c0) {
#pragma unroll
    for (int q = 0; q < 4; q++) { acc[q][0] = 0ull; acc[q][1] = 0ull; }
#pragma unroll 4
    for (int k = 0; k < 64; k++) {
        float a[4];
#pragma unroll
        for (int r = 0; r < 4; r++) {
            float v = A[(r0 + r) * 64 + k];
            if (FA) v = ((r0 + r == k) ? 1.5f : 0.0f) - 0.5f * v;
            a[r] = v;
        }
        ull bb[2];
        if (FB) {
            float4 bv = *reinterpret_cast<const float4*>(Bm + k * 64 + c0);
            bv.x = ((k == c0)     ? 1.5f : 0.0f) - 0.5f * bv.x;
            bv.y = ((k == c0 + 1) ? 1.5f : 0.0f) - 0.5f * bv.y;
            bv.z = ((k == c0 + 2) ? 1.5f : 0.0f) - 0.5f * bv.z;
            bv.w = ((k == c0 + 3) ? 1.5f : 0.0f) - 0.5f * bv.w;
            bb[0] = pack2(bv.x, bv.y);
            bb[1] = pack2(bv.z, bv.w);
        } else {
            float4 bv = *reinterpret_cast<const float4*>(Bm + k * 64 + c0);
            bb[0] = pack2(bv.x, bv.y);
            bb[1] = pack2(bv.z, bv.w);
        }
#pragma unroll
        for (int r = 0; r < 4; r++) {
            ull a2 = dup2(a[r]);
            ffma2(acc[r][0], bb[0], a2);
            ffma2(acc[r][1], bb[1], a2);
        }
    }
}

__device__ __forceinline__ void mm_store(const ull acc[4][2], float* __restrict__ Cm,
                                         int r0, int c0) {
#pragma unroll
    for (int r = 0; r < 4; r++) {
        ull* dst = reinterpret_cast<ull*>(Cm + (r0 + r) * 64 + c0);
        dst[0] = acc[r][0]; dst[1] = acc[r][1];
    }
}

// ---------------------------------------------------------------------------
// Kernel 2: reduce partials -> cov -> Newton-Schulz sqrt -> MLP -> gate
// ---------------------------------------------------------------------------
__global__ void __launch_bounds__(256) ns_kernel(const float* __restrict__ gw1,
                                                 const float* __restrict__ gb1,
                                                 const float* __restrict__ gw2,
                                                 const float* __restrict__ gb2) {
    __shared__ __align__(16) float s0[4096];
    __shared__ __align__(16) float s1[4096];
    __shared__ __align__(16) float s2[4096];
    const int bi  = blockIdx.x;
    const int tid = threadIdx.x;
    const int ti = tid >> 4, tj = tid & 15;
    const int r0 = 4 * ti, c0 = 4 * tj;

    {
        const float4* gp = reinterpret_cast<const float4*>(g_gram_part) + bi * 1024;
#pragma unroll
        for (int it = 0; it < 4; it++) {
            int e = it * 256 + tid;
            float4 a4 = make_float4(0.f, 0.f, 0.f, 0.f);
#pragma unroll
            for (int c = 0; c < KSPLIT; c++) {
                float4 v = gp[(size_t)c * (B_ * 1024) + e];
                a4.x += v.x; a4.y += v.y; a4.z += v.z; a4.w += v.w;
            }
            reinterpret_cast<float4*>(s0)[e] = a4;
        }
    }
    if (tid < 64) {
        float s = 0.f;
#pragma unroll
        for (int c = 0; c < KSPLIT; c++) s += g_sum_part[(c * B_ + bi) * C_ + tid];
        s2[tid] = s * (1.0f / M_);
    }
    __syncthreads();
    {
        const float invM = 1.0f / M_;
        for (int e = tid; e < 4096; e += 256) {
            int r = e >> 6, c = e & 63;
            s0[e] = s0[e] * invM - s2[r] * s2[c];
        }
    }
    __syncthreads();
    if (tid < 32) {
        float t = s0[tid * 65] + s0[(tid + 32) * 65];
#pragma unroll
        for (int o = 16; o > 0; o >>= 1) t += __shfl_xor_sync(0xffffffffu, t, o);
        if (tid == 0) s2[64] = t;
    }
    __syncthreads();
    const float normA = s2[64];
    const float rnorm = 1.0f / normA;
    for (int e = tid; e < 4096; e += 256) {
        int r = e >> 6, c = e & 63;
        float a = s0[e] * rnorm;
        s0[e] = a;
        s1[e] = ((r == c) ? 1.5f : 0.0f) - 0.5f * a;
    }
    __syncthreads();
    {
        ull acc[4][2];
        mm64<false, false>(acc, s0, s1, r0, c0);
        mm_store(acc, s2, r0, c0);
    }
    __syncthreads();
    float* Y = s2; float* Z = s1; float* T = s0;
    for (int it = 0; it < 3; it++) {
        ull accT[4][2];
        mm64<true, false>(accT, Z, Y, r0, c0);
        mm_store(accT, T, r0, c0);
        __syncthreads();
        ull accY[4][2], accZ[4][2];
        mm64<false, false>(accY, Y, T, r0, c0);
        mm64<false, false>(accZ, T, Z, r0, c0);
        __syncthreads();
        mm_store(accY, Y, r0, c0);
        mm_store(accZ, Z, r0, c0);
        __syncthreads();
    }
    {
        ull acc[4][2];
        mm64<false, false>(acc, Z, Y, r0, c0);
        mm_store(acc, T, r0, c0);
    }
    __syncthreads();
    {
        ull acc[4][2];
        mm64<false, true>(acc, Y, T, r0, c0);
        mm_store(acc, s1, r0, c0);
    }
    __syncthreads();
    const float scale_s = sqrtf(normA) * (1.0f / 64.0f);
    if (tid < 64) {
        float s = 0.f;
#pragma unroll 8
        for (int i = 0; i < 64; i++) s += s1[i * 64 + tid];
        s0[tid] = s * scale_s;
    }
    __syncthreads();
    if (tid < 8) {
        float h = gb1[tid];
        const float* wr = gw1 + tid * 64;
        for (int j = 0; j < 64; j++) h += s0[j] * wr[j];
        s0[64 + tid] = fmaxf(h, 0.f);
    }
    __syncthreads();
    if (tid < 64) {
        float g = gb2[tid];
        const float* wr = gw2 + tid * 8;
#pragma unroll
        for (int r = 0; r < 8; r++) g += s0[64 + r] * wr[r];
        g_gate[bi * C_ + tid] = 1.0f / (1.0f + expf(-g));
    }
}

// ---------------------------------------------------------------------------
// Kernel 3: out = x * gate[b][c]
// ---------------------------------------------------------------------------
__global__ void __launch_bounds__(256) scale_kernel(const float* __restrict__ x,
                                                    float* __restrict__ out) {
    const int total4 = B_ * C_ * (M_ / 4);
    int i = blockIdx.x * blockDim.x + threadIdx.x;
    if (i >= total4) return;
    int bc = i / (M_ / 4);
    float g = __ldg(&g_gate[bc]);
    float4 v = reinterpret_cast<const float4*>(x)[i];
    v.x *= g; v.y *= g; v.z *= g; v.w *= g;
    reinterpret_cast<float4*>(out)[i] = v;
}

extern "C" void kernel_launch(void* const* d_in, const int* in_sizes, int n_in,
                              void* d_out, int out_size) {
    const float* x  = (const float*)d_in[0];
    const float* w1 = (const float*)d_in[1];
    const float* b1 = (const float*)d_in[2];
    const float* w2 = (const float*)d_in[3];
    const float* b2 = (const float*)d_in[4];
    float* out = (float*)d_out;

    dim3 g1(KSPLIT, B_);
    gram_tc<<<g1, 256>>>(x);
    ns_kernel<<<B_, 256>>>(w1, b1, w2, b2);
    const int total4 = B_ * C_ * (M_ / 4);
    scale_kernel<<<(total4 + 255) / 256, 256>>>(x, out);
}